// round 12
// baseline (speedup 1.0000x reference)
#include <cuda_runtime.h>
#include <cstdint>

#define FULL 0xffffffffu

constexpr int   NTAG    = 32;
constexpr int   CH      = 8;              // steps per chunk
constexpr int   NS      = 4;              // phi ring slots (chunks)
constexpr int   STEPF   = NTAG * NTAG;    // 1024 floats per step
constexpr int   CHUNK_B = CH * STEPF * 4; // 32768 bytes
constexpr int   ARING   = 24;             // alpha ring slots (steps)
constexpr float NEGINF  = -1e4f;

__device__ __forceinline__ void barsync() {
    asm volatile("bar.sync 0;" ::: "memory");
}

// bool-array accessor: mode 0 = int32, 1 = uint8, 2 = float32
__device__ __forceinline__ bool getb(const void* p, int idx, int mode) {
    if (mode == 0) return ((const int*)p)[idx] != 0;
    if (mode == 1) return ((const uint8_t*)p)[idx] != 0;
    return ((const float*)p)[idx] != 0.0f;
}

// ---- value-only step: max_i alpha[i] + (pht[i][j] [+ep]), pht = phi+tp pre-fused ----
template<bool END>
__device__ __forceinline__ float vval(const float* __restrict__ ph,
                                      float my_alpha, float epj)
{
    float s[NTAG];
#pragma unroll
    for (int i = 0; i < NTAG; ++i) {
        float av = __shfl_sync(FULL, my_alpha, i);
        float e  = ph[i * NTAG];
        if (END) e += epj;
        s[i] = av + e;
    }
    float m[16];
#pragma unroll
    for (int k = 0; k < 16; ++k) m[k] = fmaxf(s[2*k], s[2*k+1]);
#pragma unroll
    for (int k = 0; k < 8; ++k)  m[k] = fmaxf(m[2*k], m[2*k+1]);
#pragma unroll
    for (int k = 0; k < 4; ++k)  m[k] = fmaxf(m[2*k], m[2*k+1]);
#pragma unroll
    for (int k = 0; k < 2; ++k)  m[k] = fmaxf(m[2*k], m[2*k+1]);
    return fmaxf(m[0], m[1]);
}

// ---- index-only step: first-argmax via left-biased select tree (identical op order) ----
template<bool END>
__device__ __forceinline__ int vidx(const float* __restrict__ ph,
                                    float a_self, float epj)
{
    float s[NTAG];
#pragma unroll
    for (int i = 0; i < NTAG; ++i) {
        float av = __shfl_sync(FULL, a_self, i);
        float e  = ph[i * NTAG];
        if (END) e += epj;
        s[i] = av + e;
    }
    float v[16]; int ix[16];
#pragma unroll
    for (int k = 0; k < 16; ++k) {
        bool c = s[2*k+1] > s[2*k];
        v[k] = c ? s[2*k+1] : s[2*k];  ix[k] = c ? 2*k+1 : 2*k;
    }
#pragma unroll
    for (int k = 0; k < 8; ++k) {
        bool c = v[2*k+1] > v[2*k];
        v[k] = c ? v[2*k+1] : v[2*k];  ix[k] = c ? ix[2*k+1] : ix[2*k];
    }
#pragma unroll
    for (int k = 0; k < 4; ++k) {
        bool c = v[2*k+1] > v[2*k];
        v[k] = c ? v[2*k+1] : v[2*k];  ix[k] = c ? ix[2*k+1] : ix[2*k];
    }
#pragma unroll
    for (int k = 0; k < 2; ++k) {
        bool c = v[2*k+1] > v[2*k];
        v[k] = c ? v[2*k+1] : v[2*k];  ix[k] = c ? ix[2*k+1] : ix[2*k];
    }
    return (v[1] > v[0]) ? ix[1] : ix[0];
}

__global__ void __launch_bounds__(160, 1)
ConstrainedDecoder_kernel(const float* __restrict__ lp,
                          const void* __restrict__ mask,
                          const void* __restrict__ startc,
                          const void* __restrict__ endc,
                          const void* __restrict__ transc,
                          float* __restrict__ out,
                          int B, int T)
{
    extern __shared__ char smem[];
    float*   buf   = (float*)smem;                                       // NS*32KB phi ring
    float*   aring = (float*)(smem + NS * CHUNK_B);                      // ARING*32 floats
    uint8_t* back  = (uint8_t*)(smem + NS * CHUNK_B + ARING * NTAG * 4); // T*32 bytes
    int*     xsh   = (int*)(back + (size_t)T * NTAG);                    // final tag index

    const int b   = blockIdx.x;
    const int tid = threadIdx.x;
    const int j   = tid & 31;
    const int wid = tid >> 5;   // 0=compute, 1/2=argmax halves, 3/4=producers

    // ---- detect bool encoding from mask[0] (guaranteed true) ----
    uint32_t w0 = ((const uint32_t*)mask)[0];
    const int mode = (w0 == 1u) ? 0 : (w0 == 0x01010101u) ? 1 : 2;

    // ---- sequence length (mask prefix-true); all warps compute it ----
    int len = 0;
    {
        const size_t mbase = (size_t)b * T;
        for (int k = j; k < T; k += 32)
            if (getb(mask, (int)(mbase + k), mode)) len = k + 1;
#pragma unroll
        for (int off = 16; off; off >>= 1)
            len = max(len, __shfl_xor_sync(FULL, len, off));
    }
    if (len < 1) len = 1;
    if (len > T) len = T;
    const int nchunk = (len + CH - 1) / CH;
    const int lenm1  = len - 1;

    if (wid >= 3) {
        // ============ producer warps: LDG.128 -> regs -> (fuse tp) -> STS.128 ============
        const int p = wid - 3;   // 0 or 1: interleaved 512B blocks

        // row masks of transition constraints: mytm = bits j of row (lane id)
        uint32_t mytm = 0;
        for (int i = 0; i < NTAG; ++i) {
            uint32_t m = __ballot_sync(FULL, getb(transc, i * NTAG + j, mode));
            if (i == j) mytm = m;
        }

        const uint4* gsrc = (const uint4*)(lp + (size_t)b * T * STEPF);
        uint4 v[32];

        auto ldg = [&](int cc) {
            const uint4* s = gsrc + (size_t)cc * 2048 + j;
#pragma unroll
            for (int k = 0; k < 32; ++k) {
                int lin = 2 * k + p;        // 512B block index within chunk (0..63)
                v[k] = s[(size_t)lin * 32];
            }
        };
        auto sts = [&](int cc) {
            char* dstc = (char*)buf + (size_t)(cc & (NS - 1)) * CHUNK_B;
#pragma unroll
            for (int k = 0; k < 32; ++k) {
                int lin = 2 * k + p;
                uint4 d = v[k];
                if (!(cc == 0 && lin < 8)) {   // skip fuse for global step 0 (start step raw)
                    // element base e0 = lin*128 + j*4 -> i = (lin*4 + (j>>3)) & 31, jcol = (j&7)*4
                    int i  = ((lin << 2) + (j >> 3)) & 31;
                    uint32_t m = __shfl_sync(FULL, mytm, i);
                    int jc = (j & 7) << 2;
                    float f0 = __uint_as_float(d.x) + (((m >> (jc + 0)) & 1u) ? 0.0f : NEGINF);
                    float f1 = __uint_as_float(d.y) + (((m >> (jc + 1)) & 1u) ? 0.0f : NEGINF);
                    float f2 = __uint_as_float(d.z) + (((m >> (jc + 2)) & 1u) ? 0.0f : NEGINF);
                    float f3 = __uint_as_float(d.w) + (((m >> (jc + 3)) & 1u) ? 0.0f : NEGINF);
                    d.x = __float_as_uint(f0); d.y = __float_as_uint(f1);
                    d.z = __float_as_uint(f2); d.w = __float_as_uint(f3);
                }
                *(uint4*)(dstc + (size_t)lin * 512 + (size_t)j * 16) = d;
            }
        };

        ldg(0);
        sts(0);                    // startup: exposed DRAM latency once
        if (nchunk > 1) ldg(1);

        for (int c = 0; c <= nchunk; ++c) {
            barsync();             // phase c: compute consumes chunk c
            if (c + 1 < nchunk) {
                sts(c + 1);        // regs (loaded in phase c-1) -> slot (c+1)%4
                if (c + 2 < nchunk) ldg(c + 2);
            }
        }
        barsync();                 // final output handoff
    } else if (wid == 0) {
        // ============ compute warp: value recurrence on fused phi ============
        const float sp = getb(startc, j, mode) ? 0.0f : NEGINF;
        const float ep = getb(endc,   j, mode) ? 0.0f : NEGINF;

        float my_alpha = 0.0f;

        for (int c = 0; c <= nchunk; ++c) {
            barsync();   // chunk c resident + fused
            if (c >= nchunk) continue;
            const float* pb = buf + (size_t)(c & (NS - 1)) * CH * STEPF + j;

            int t0 = c * CH;
            int t1 = t0 + CH; if (t1 > len) t1 = len;

            if (c == 0) {
                // t=0 uses RAW phi (producers skipped fusing it)
                float m = pb[0];
#pragma unroll
                for (int i = 1; i < NTAG; ++i) m = fmaxf(m, pb[i * NTAG]);
                my_alpha = m + sp;
                if (len == 1) my_alpha += ep;
                aring[j] = my_alpha;   // slot 0
                t0 = 1;
            }

            int tend = t1 < lenm1 ? t1 : lenm1;
#pragma unroll 2
            for (int t = t0; t < tend; ++t) {
                const float* ph = pb + (size_t)(t & (CH - 1)) * STEPF;
                my_alpha = vval<false>(ph, my_alpha, ep);
                aring[(t % ARING) * NTAG + j] = my_alpha;
            }

            if (len >= 2 && (lenm1 >> 3) == c) {
                const float* ph = pb + (size_t)(lenm1 & (CH - 1)) * STEPF;
                my_alpha = vval<true>(ph, my_alpha, ep);
                aring[(lenm1 % ARING) * NTAG + j] = my_alpha;
            }
        }

        // final max / first-argmax over tags
        float v = my_alpha; int ix = j;
#pragma unroll
        for (int off = 16; off; off >>= 1) {
            float ov = __shfl_xor_sync(FULL, v, off);
            int   oi = __shfl_xor_sync(FULL, ix, off);
            if (ov > v || (ov == v && oi < ix)) { v = ov; ix = oi; }
        }
        if (j == 0) { out[b] = v; *xsh = ix; }
        barsync();  // final output handoff
    } else {
        // ============ argmax warps (wid 1,2): backpointers, 1 chunk behind ============
        const float ep = getb(endc, j, mode) ? 0.0f : NEGINF;
        const int   half = wid - 1;   // 0: steps [0,4) of chunk, 1: steps [4,8)

        for (int c = 0; c <= nchunk; ++c) {
            barsync();
            int cc = c - 1;
            if (cc < 0) continue;
            const float* pb = buf + (size_t)(cc & (NS - 1)) * CH * STEPF + j;

            int base = cc * CH + half * 4;
            int t0 = base; if (t0 < 1) t0 = 1;
            int t1 = base + 4; if (t1 > len) t1 = len;
            int tend = t1 < lenm1 ? t1 : lenm1;

#pragma unroll 2
            for (int t = t0; t < tend; ++t) {
                const float* ph = pb + (size_t)(t & (CH - 1)) * STEPF;
                float a_self = aring[((t - 1) % ARING) * NTAG + j];
                int bi = vidx<false>(ph, a_self, ep);
                back[(size_t)t * NTAG + j] = (uint8_t)bi;
            }

            if (len >= 2 && (lenm1 >> 3) == cc && (((lenm1 >> 2) & 1) == half)) {
                const float* ph = pb + (size_t)(lenm1 & (CH - 1)) * STEPF;
                float a_self = aring[((lenm1 - 1) % ARING) * NTAG + j];
                int bi = vidx<true>(ph, a_self, ep);
                back[(size_t)lenm1 * NTAG + j] = (uint8_t)bi;
            }
        }

        barsync();  // xsh + back complete

        float* out_tags = out + B;   // [B, T]
        if (wid == 2) {
            for (int k = len + j; k < T; k += 32)
                out_tags[(size_t)b * T + k] = -1.0f;
        } else if (j == 0) {
            int tag = *xsh;
            out_tags[(size_t)b * T + lenm1] = (float)tag;
            for (int tt = lenm1; tt >= 1; --tt) {
                tag = back[(size_t)tt * NTAG + tag];
                out_tags[(size_t)b * T + tt - 1] = (float)tag;
            }
        }
    }
}

extern "C" void kernel_launch(void* const* d_in, const int* in_sizes, int n_in,
                              void* d_out, int out_size)
{
    const float* lp   = (const float*)d_in[0];
    const void*  mask = d_in[1];
    const void*  sc   = d_in[2];
    const void*  ec   = d_in[3];
    const void*  tc   = d_in[4];

    const int BT = in_sizes[1];      // B*T elements in mask
    int B = out_size - BT;           // out = [B] mlp + [B*T] tags
    if (B <= 0) B = 64;
    const int T = BT / B;

    size_t smem = (size_t)NS * CHUNK_B + (size_t)ARING * NTAG * 4
                + (size_t)T * NTAG + 64;
    cudaFuncSetAttribute(ConstrainedDecoder_kernel,
                         cudaFuncAttributeMaxDynamicSharedMemorySize, (int)smem);

    ConstrainedDecoder_kernel<<<B, 160, smem>>>(lp, mask, sc, ec, tc,
                                                (float*)d_out, B, T);
}

// round 13
// speedup vs baseline: 1.2861x; 1.2861x over previous
#include <cuda_runtime.h>
#include <cstdint>

#define FULL 0xffffffffu

constexpr int   NTAG    = 32;
constexpr int   CH      = 8;              // steps per chunk
constexpr int   NS      = 4;              // phi ring slots (chunks)
constexpr int   STEPF   = NTAG * NTAG;    // 1024 floats per step
constexpr int   CHUNK_B = CH * STEPF * 4; // 32768 bytes
constexpr int   ARING   = 32;             // alpha ring slots (pow2)
constexpr float NEGINF  = -1e4f;

__device__ __forceinline__ void barsync() {
    asm volatile("bar.sync 0;" ::: "memory");
}

// bool-array accessor: mode 0 = int32, 1 = uint8, 2 = float32
__device__ __forceinline__ bool getb(const void* p, int idx, int mode) {
    if (mode == 0) return ((const int*)p)[idx] != 0;
    if (mode == 1) return ((const uint8_t*)p)[idx] != 0;
    return ((const float*)p)[idx] != 0.0f;
}

// load full 32-float alpha vector via 8 broadcast LDS.128 (no shuffles)
__device__ __forceinline__ void load_alpha(const float* __restrict__ aslot, float* a) {
    const uint4* q = (const uint4*)aslot;
#pragma unroll
    for (int k = 0; k < 8; ++k) {
        uint4 v = q[k];
        a[4*k+0] = __uint_as_float(v.x);
        a[4*k+1] = __uint_as_float(v.y);
        a[4*k+2] = __uint_as_float(v.z);
        a[4*k+3] = __uint_as_float(v.w);
    }
}

// ---- value-only step: max_i a[i] + (pht[i][j] [+ep]); pht = phi+tp pre-fused ----
// Op order matches reference: alpha + ((phi+tp)[+ep]); FMNMX tree == ref max bitwise.
template<bool END>
__device__ __forceinline__ float vval(const float* __restrict__ ph,
                                      const float* a, float epj)
{
    float s[NTAG];
#pragma unroll
    for (int i = 0; i < NTAG; ++i) {
        float e = ph[i * NTAG];
        if (END) e += epj;
        s[i] = a[i] + e;
    }
    float m[16];
#pragma unroll
    for (int k = 0; k < 16; ++k) m[k] = fmaxf(s[2*k], s[2*k+1]);
#pragma unroll
    for (int k = 0; k < 8; ++k)  m[k] = fmaxf(m[2*k], m[2*k+1]);
#pragma unroll
    for (int k = 0; k < 4; ++k)  m[k] = fmaxf(m[2*k], m[2*k+1]);
#pragma unroll
    for (int k = 0; k < 2; ++k)  m[k] = fmaxf(m[2*k], m[2*k+1]);
    return fmaxf(m[0], m[1]);
}

// ---- index-only step: first-argmax via left-biased select tree (identical op order) ----
template<bool END>
__device__ __forceinline__ int vidx(const float* __restrict__ ph,
                                    const float* a, float epj)
{
    float s[NTAG];
#pragma unroll
    for (int i = 0; i < NTAG; ++i) {
        float e = ph[i * NTAG];
        if (END) e += epj;
        s[i] = a[i] + e;
    }
    float v[16]; int ix[16];
#pragma unroll
    for (int k = 0; k < 16; ++k) {
        bool c = s[2*k+1] > s[2*k];
        v[k] = c ? s[2*k+1] : s[2*k];  ix[k] = c ? 2*k+1 : 2*k;
    }
#pragma unroll
    for (int k = 0; k < 8; ++k) {
        bool c = v[2*k+1] > v[2*k];
        v[k] = c ? v[2*k+1] : v[2*k];  ix[k] = c ? ix[2*k+1] : ix[2*k];
    }
#pragma unroll
    for (int k = 0; k < 4; ++k) {
        bool c = v[2*k+1] > v[2*k];
        v[k] = c ? v[2*k+1] : v[2*k];  ix[k] = c ? ix[2*k+1] : ix[2*k];
    }
#pragma unroll
    for (int k = 0; k < 2; ++k) {
        bool c = v[2*k+1] > v[2*k];
        v[k] = c ? v[2*k+1] : v[2*k];  ix[k] = c ? ix[2*k+1] : ix[2*k];
    }
    return (v[1] > v[0]) ? ix[1] : ix[0];
}

__global__ void __launch_bounds__(224, 1)
ConstrainedDecoder_kernel(const float* __restrict__ lp,
                          const void* __restrict__ mask,
                          const void* __restrict__ startc,
                          const void* __restrict__ endc,
                          const void* __restrict__ transc,
                          float* __restrict__ out,
                          int B, int T)
{
    extern __shared__ char smem[];
    float*   buf   = (float*)smem;                                       // NS*32KB phi ring
    float*   aring = (float*)(smem + NS * CHUNK_B);                      // ARING*32 floats
    uint8_t* back  = (uint8_t*)(smem + NS * CHUNK_B + ARING * NTAG * 4); // T*32 bytes
    int*     xsh   = (int*)(back + (size_t)T * NTAG);                    // final tag index

    const int b   = blockIdx.x;
    const int tid = threadIdx.x;
    const int j   = tid & 31;
    const int wid = tid >> 5;   // 0=compute, 1/2=argmax halves, 3..6=producers

    // ---- detect bool encoding from mask[0] (guaranteed true) ----
    uint32_t w0 = ((const uint32_t*)mask)[0];
    const int mode = (w0 == 1u) ? 0 : (w0 == 0x01010101u) ? 1 : 2;

    // ---- sequence length (mask prefix-true); all warps compute it ----
    int len = 0;
    {
        const size_t mbase = (size_t)b * T;
        for (int k = j; k < T; k += 32)
            if (getb(mask, (int)(mbase + k), mode)) len = k + 1;
#pragma unroll
        for (int off = 16; off; off >>= 1)
            len = max(len, __shfl_xor_sync(FULL, len, off));
    }
    if (len < 1) len = 1;
    if (len > T) len = T;
    const int nchunk = (len + CH - 1) / CH;
    const int lenm1  = len - 1;

    if (wid >= 3) {
        // ============ producer warps (4): LDG.128 -> regs -> fuse tp -> STS.128 ============
        const int p = wid - 3;   // 0..3: lin ≡ p (mod 4)

        // row masks of transition constraints: mytm = row (lane id) allowed-bits over j
        uint32_t mytm = 0;
        for (int i = 0; i < NTAG; ++i) {
            uint32_t m = __ballot_sync(FULL, getb(transc, i * NTAG + j, mode));
            if (i == j) mytm = m;
        }

        const uint4* gsrc = (const uint4*)(lp + (size_t)b * T * STEPF);
        uint4 v[16];

        auto ldg = [&](int cc) {
            const uint4* s = gsrc + (size_t)cc * 2048 + j;
#pragma unroll
            for (int k = 0; k < 16; ++k) {
                int lin = 4 * k + p;        // 512B block index within chunk (0..63)
                v[k] = s[(size_t)lin * 32];
            }
        };
        auto sts = [&](int cc) {
            char* dstc = (char*)buf + (size_t)(cc & (NS - 1)) * CHUNK_B;
#pragma unroll
            for (int k = 0; k < 16; ++k) {
                int lin = 4 * k + p;
                uint4 d = v[k];
                if (!(cc == 0 && lin < 8)) {   // global step 0 stays raw (start step)
                    // uint4 covers floats [lin*128 + j*4 .. +3]: i = (lin*4 + (j>>3)) & 31
                    int i  = ((lin << 2) + (j >> 3)) & 31;
                    uint32_t m = __shfl_sync(FULL, mytm, i);
                    int jc = (j & 7) << 2;
                    d.x = __float_as_uint(__uint_as_float(d.x) + (((m >> (jc + 0)) & 1u) ? 0.0f : NEGINF));
                    d.y = __float_as_uint(__uint_as_float(d.y) + (((m >> (jc + 1)) & 1u) ? 0.0f : NEGINF));
                    d.z = __float_as_uint(__uint_as_float(d.z) + (((m >> (jc + 2)) & 1u) ? 0.0f : NEGINF));
                    d.w = __float_as_uint(__uint_as_float(d.w) + (((m >> (jc + 3)) & 1u) ? 0.0f : NEGINF));
                }
                *(uint4*)(dstc + (size_t)lin * 512 + (size_t)j * 16) = d;
            }
        };

        ldg(0);
        sts(0);                    // startup: one exposed DRAM latency
        if (nchunk > 1) ldg(1);

        for (int c = 0; c <= nchunk; ++c) {
            barsync();             // phase c: compute consumes chunk c
            if (c + 1 < nchunk) {
                sts(c + 1);        // regs (loaded last phase) -> slot (c+1)%4
                if (c + 2 < nchunk) ldg(c + 2);
            }
        }
        barsync();                 // final output handoff
    } else if (wid == 0) {
        // ============ compute warp: value recurrence, alpha via smem broadcast ============
        const float sp = getb(startc, j, mode) ? 0.0f : NEGINF;
        const float ep = getb(endc,   j, mode) ? 0.0f : NEGINF;

        float last_alpha = 0.0f;   // this lane's alpha (for final reduction)

        for (int c = 0; c <= nchunk; ++c) {
            barsync();   // chunk c resident + fused
            if (c >= nchunk) continue;
            const float* pb = buf + (size_t)(c & (NS - 1)) * CH * STEPF + j;

            int t0 = c * CH;
            int t1 = t0 + CH; if (t1 > len) t1 = len;

            if (c == 0) {
                // t=0 uses RAW phi: alpha0[j] = max_i phi0[i][j] + sp (+ep if len==1)
                float m = pb[0];
#pragma unroll
                for (int i = 1; i < NTAG; ++i) m = fmaxf(m, pb[i * NTAG]);
                last_alpha = m + sp;
                if (len == 1) last_alpha += ep;
                aring[j] = last_alpha;   // slot 0
                t0 = 1;
            }

            int tend = t1 < lenm1 ? t1 : lenm1;
#pragma unroll 2
            for (int t = t0; t < tend; ++t) {
                const float* ph = pb + (size_t)(t & (CH - 1)) * STEPF;
                float a[NTAG];
                load_alpha(aring + ((t - 1) & (ARING - 1)) * NTAG, a);
                last_alpha = vval<false>(ph, a, ep);
                aring[(t & (ARING - 1)) * NTAG + j] = last_alpha;
            }

            if (len >= 2 && (lenm1 >> 3) == c) {
                const float* ph = pb + (size_t)(lenm1 & (CH - 1)) * STEPF;
                float a[NTAG];
                load_alpha(aring + ((lenm1 - 1) & (ARING - 1)) * NTAG, a);
                last_alpha = vval<true>(ph, a, ep);
                aring[(lenm1 & (ARING - 1)) * NTAG + j] = last_alpha;
            }
        }

        // final max / first-argmax over tags (one-time shuffles OK)
        float v = last_alpha; int ix = j;
#pragma unroll
        for (int off = 16; off; off >>= 1) {
            float ov = __shfl_xor_sync(FULL, v, off);
            int   oi = __shfl_xor_sync(FULL, ix, off);
            if (ov > v || (ov == v && oi < ix)) { v = ov; ix = oi; }
        }
        if (j == 0) { out[b] = v; *xsh = ix; }
        barsync();  // final output handoff
    } else {
        // ============ argmax warps (wid 1,2): backpointers, 1 chunk behind ============
        const float ep = getb(endc, j, mode) ? 0.0f : NEGINF;
        const int   half = wid - 1;   // 0: steps [0,4) of chunk, 1: steps [4,8)

        for (int c = 0; c <= nchunk; ++c) {
            barsync();
            int cc = c - 1;
            if (cc < 0) continue;
            const float* pb = buf + (size_t)(cc & (NS - 1)) * CH * STEPF + j;

            int base = cc * CH + half * 4;
            int t0 = base; if (t0 < 1) t0 = 1;
            int t1 = base + 4; if (t1 > len) t1 = len;
            int tend = t1 < lenm1 ? t1 : lenm1;

#pragma unroll 2
            for (int t = t0; t < tend; ++t) {
                const float* ph = pb + (size_t)(t & (CH - 1)) * STEPF;
                float a[NTAG];
                load_alpha(aring + ((t - 1) & (ARING - 1)) * NTAG, a);
                int bi = vidx<false>(ph, a, ep);
                back[(size_t)t * NTAG + j] = (uint8_t)bi;
            }

            if (len >= 2 && (lenm1 >> 3) == cc && (((lenm1 >> 2) & 1) == half)) {
                const float* ph = pb + (size_t)(lenm1 & (CH - 1)) * STEPF;
                float a[NTAG];
                load_alpha(aring + ((lenm1 - 1) & (ARING - 1)) * NTAG, a);
                int bi = vidx<true>(ph, a, ep);
                back[(size_t)lenm1 * NTAG + j] = (uint8_t)bi;
            }
        }

        barsync();  // xsh + back complete

        float* out_tags = out + B;   // [B, T]
        if (wid == 2) {
            for (int k = len + j; k < T; k += 32)
                out_tags[(size_t)b * T + k] = -1.0f;
        } else if (j == 0) {
            int tag = *xsh;
            out_tags[(size_t)b * T + lenm1] = (float)tag;
            for (int tt = lenm1; tt >= 1; --tt) {
                tag = back[(size_t)tt * NTAG + tag];
                out_tags[(size_t)b * T + tt - 1] = (float)tag;
            }
        }
    }
}

extern "C" void kernel_launch(void* const* d_in, const int* in_sizes, int n_in,
                              void* d_out, int out_size)
{
    const float* lp   = (const float*)d_in[0];
    const void*  mask = d_in[1];
    const void*  sc   = d_in[2];
    const void*  ec   = d_in[3];
    const void*  tc   = d_in[4];

    const int BT = in_sizes[1];      // B*T elements in mask
    int B = out_size - BT;           // out = [B] mlp + [B*T] tags
    if (B <= 0) B = 64;
    const int T = BT / B;

    size_t smem = (size_t)NS * CHUNK_B + (size_t)ARING * NTAG * 4
                + (size_t)T * NTAG + 64;
    cudaFuncSetAttribute(ConstrainedDecoder_kernel,
                         cudaFuncAttributeMaxDynamicSharedMemorySize, (int)smem);

    ConstrainedDecoder_kernel<<<B, 224, smem>>>(lp, mask, sc, ec, tc,
                                                (float*)d_out, B, T);
}